// round 2
// baseline (speedup 1.0000x reference)
#include <cuda_runtime.h>
#include <cuda_bf16.h>
#include <cstdint>

// Problem constants
#define BB   8
#define NT   2          // edge types
#define NN   2000       // nodes
#define ENN  4000       // NT * NN
#define NNZE 32000      // nnz per (b, type)
#define LL   8
#define DD   64
#define LD   512        // L*D
#define SEG  (BB*NT)    // 16 segments
#define NPB  8          // nodes per block
#define KDIM 192        // 3*D
#define ASTR 196        // padded row stride for a-matrix in smem
#define RSTR 68         // padded row stride for r*cur (16B aligned)

// ---------------- device scratch ----------------
__device__ int   g_count [SEG * NN];
__device__ int   g_cursor[SEG * NN];
__device__ int   g_rowptr[SEG * (NN + 1)];
__device__ float g_ev    [SEG * NNZE];
__device__ int   g_ec    [SEG * NNZE];
__device__ __align__(16) float g_Wt[3 * KDIM * DD];   // [mat][i][o]

// ---------------- f32x2 helpers ----------------
typedef unsigned long long u64t;

__device__ __forceinline__ u64t dupf(float v) {
    u64t r;
    asm("mov.b64 %0, {%1, %1};" : "=l"(r) : "f"(v));
    return r;
}
__device__ __forceinline__ void ffma2(u64t& d, u64t a, u64t b) {
    asm("fma.rn.f32x2 %0, %1, %2, %0;" : "+l"(d) : "l"(a), "l"(b));
}
__device__ __forceinline__ float2 unpk(u64t v) {
    float2 f;
    asm("mov.b64 {%0, %1}, %2;" : "=f"(f.x), "=f"(f.y) : "l"(v));
    return f;
}

// ---------------- CSR build ----------------
__global__ void k_zero_counts() {
    int i = blockIdx.x * blockDim.x + threadIdx.x;
    if (i < SEG * NN) g_count[i] = 0;
}

__global__ void k_hist(const int* __restrict__ rows) {
    int idx = blockIdx.x * blockDim.x + threadIdx.x;
    if (idx >= SEG * NNZE) return;
    int seg = idx / NNZE;
    atomicAdd(&g_count[seg * NN + rows[idx]], 1);
}

__global__ void k_scan() {
    int seg = blockIdx.x;
    int t   = threadIdx.x;
    __shared__ int sm2[256];
    int c[8];
    int ts = 0;
    int base = seg * NN;
#pragma unroll
    for (int j = 0; j < 8; ++j) {
        int idx = t * 8 + j;
        c[j] = (idx < NN) ? g_count[base + idx] : 0;
        ts += c[j];
    }
    sm2[t] = ts;
    __syncthreads();
    for (int off = 1; off < 256; off <<= 1) {
        int v = sm2[t];
        if (t >= off) v += sm2[t - off];
        __syncthreads();
        sm2[t] = v;
        __syncthreads();
    }
    int run = sm2[t] - ts;
#pragma unroll
    for (int j = 0; j < 8; ++j) {
        int idx = t * 8 + j;
        if (idx < NN) {
            g_rowptr[seg * (NN + 1) + idx] = run;
            g_cursor[base + idx] = run;
            run += c[j];
        }
    }
    if (t == 255) g_rowptr[seg * (NN + 1) + NN] = sm2[255];
}

__global__ void k_scatter(const float* __restrict__ vals,
                          const int*   __restrict__ rows,
                          const int*   __restrict__ cols) {
    int idx = blockIdx.x * blockDim.x + threadIdx.x;
    if (idx >= SEG * NNZE) return;
    int seg = idx / NNZE;
    int pos = atomicAdd(&g_cursor[seg * NN + rows[idx]], 1);
    g_ev[seg * NNZE + pos] = vals[idx];
    g_ec[seg * NNZE + pos] = cols[idx];
}

// ---------------- W transpose ----------------
__global__ void k_wt(const float* __restrict__ Wr,
                     const float* __restrict__ Wz,
                     const float* __restrict__ Wh) {
    int idx = blockIdx.x * blockDim.x + threadIdx.x;
    if (idx >= 3 * KDIM * DD) return;
    int mat = idx / (KDIM * DD);
    int r   = idx - mat * (KDIM * DD);
    int i   = r / DD;
    int o   = r - i * DD;
    const float* W = (mat == 0) ? Wr : (mat == 1) ? Wz : Wh;
    g_Wt[idx] = W[o * KDIM + i];
}

// ---------------- fused SpMM + GEMM + GRU ----------------
__device__ __forceinline__ float sigm(float x) {
    return 1.0f / (1.0f + __expf(-x));
}

__global__ void __launch_bounds__(256)
k_main(const float* __restrict__ state_in,
       const float* __restrict__ state_out,
       const float* __restrict__ state_cur,
       const float* __restrict__ b_r,
       const float* __restrict__ b_z,
       const float* __restrict__ b_h,
       float* __restrict__ out) {
    extern __shared__ float smem[];
    float* As = smem;                 // [64][ASTR]: 0:64 a_in, 64:128 a_out, 128:192 cur
    float* RC = smem + 64 * ASTR;     // [64][RSTR]: r * state_cur

    const int blk  = blockIdx.x;
    const int b    = blk / (NN / NPB);
    const int nb   = (blk - b * (NN / NPB)) * NPB;
    const int tid  = threadIdx.x;
    const int w    = tid >> 5;
    const int lane = tid & 31;

    // ---------- Phase 1: SpMM gather into smem ----------
    for (int task = w; task < 16; task += 8) {
        const int node = task >> 1;
        const int type = task & 1;
        const int n    = nb + node;
        const int seg  = b * NT + type;
        const int start = g_rowptr[seg * (NN + 1) + n];
        const int end   = g_rowptr[seg * (NN + 1) + n + 1];
        const float* S  = (type == 0 ? state_in : state_out) + (size_t)b * ENN * LD;

        float4 a0 = {0,0,0,0}, a1 = {0,0,0,0}, a2 = {0,0,0,0}, a3 = {0,0,0,0};
        int   k = start;
        float v = 0.0f;
        int   c = 0;
        if (k < end) { v = g_ev[seg * NNZE + k]; c = g_ec[seg * NNZE + k]; }
        for (; k < end; ++k) {
            const float cv = v;
            const int   cc = c;
            if (k + 1 < end) {
                v = g_ev[seg * NNZE + k + 1];
                c = g_ec[seg * NNZE + k + 1];
            }
            const float4* row = reinterpret_cast<const float4*>(S + (size_t)cc * LD);
            float4 r0 = __ldg(row + lane);
            float4 r1 = __ldg(row + 32 + lane);
            float4 r2 = __ldg(row + 64 + lane);
            float4 r3 = __ldg(row + 96 + lane);
            a0.x += cv * r0.x; a0.y += cv * r0.y; a0.z += cv * r0.z; a0.w += cv * r0.w;
            a1.x += cv * r1.x; a1.y += cv * r1.y; a1.z += cv * r1.z; a1.w += cv * r1.w;
            a2.x += cv * r2.x; a2.y += cv * r2.y; a2.z += cv * r2.z; a2.w += cv * r2.w;
            a3.x += cv * r3.x; a3.y += cv * r3.y; a3.z += cv * r3.w * 0.0f + cv * r3.z; a3.w += cv * r3.w;
        }
        float4 acc[4] = {a0, a1, a2, a3};
#pragma unroll
        for (int j = 0; j < 4; ++j) {
            const int E  = j * 32 + lane;
            const int l  = E >> 4;
            const int d4 = (E & 15) * 4;
            *reinterpret_cast<float4*>(&As[(node * LL + l) * ASTR + type * DD + d4]) = acc[j];
        }
    }
    // state_cur: warp w loads node w
    {
        const int n = nb + w;
        const float4* C = reinterpret_cast<const float4*>(state_cur + (size_t)(b * NN + n) * LD);
#pragma unroll
        for (int j = 0; j < 4; ++j) {
            const int E  = j * 32 + lane;
            const int l  = E >> 4;
            const int d4 = (E & 15) * 4;
            *reinterpret_cast<float4*>(&As[(w * LL + l) * ASTR + 128 + d4]) = __ldg(C + E);
        }
    }
    __syncthreads();

    // ---------- Phase 2: fused r/z/h GEMMs with packed f32x2 FMA ----------
    // Thread tile: 4 m-rows x 4 o-cols (as 2 packed o-pairs).
    const int og = tid & 15;
    const int mg = tid >> 4;
    const int ob = og * 4;
    const int mb = mg * 4;

    const float* Wr = g_Wt;
    const float* Wz = g_Wt + KDIM * DD;
    const float* Wh = g_Wt + 2 * KDIM * DD;

    u64t ra[8], za[8], ha[8];
#pragma unroll
    for (int q = 0; q < 8; ++q) { ra[q] = 0ULL; za[q] = 0ULL; ha[q] = 0ULL; }

    // Loop A: i in [0,128): joined[i] == a[i], so accumulate all three.
#pragma unroll 2
    for (int i = 0; i < 128; ++i) {
        const ulonglong2 wr = __ldg(reinterpret_cast<const ulonglong2*>(Wr + i * DD + ob));
        const ulonglong2 wz = __ldg(reinterpret_cast<const ulonglong2*>(Wz + i * DD + ob));
        const ulonglong2 wh = __ldg(reinterpret_cast<const ulonglong2*>(Wh + i * DD + ob));
        u64t ap[4];
#pragma unroll
        for (int jm = 0; jm < 4; ++jm) ap[jm] = dupf(As[(mb + jm) * ASTR + i]);
#pragma unroll
        for (int jm = 0; jm < 4; ++jm) {
            ffma2(ra[jm * 2 + 0], ap[jm], wr.x);
            ffma2(ra[jm * 2 + 1], ap[jm], wr.y);
            ffma2(za[jm * 2 + 0], ap[jm], wz.x);
            ffma2(za[jm * 2 + 1], ap[jm], wz.y);
            ffma2(ha[jm * 2 + 0], ap[jm], wh.x);
            ffma2(ha[jm * 2 + 1], ap[jm], wh.y);
        }
    }

    // Loop B: i in [128,192): r/z use state_cur columns of As.
#pragma unroll 2
    for (int i = 128; i < KDIM; ++i) {
        const ulonglong2 wr = __ldg(reinterpret_cast<const ulonglong2*>(Wr + i * DD + ob));
        const ulonglong2 wz = __ldg(reinterpret_cast<const ulonglong2*>(Wz + i * DD + ob));
        u64t ap[4];
#pragma unroll
        for (int jm = 0; jm < 4; ++jm) ap[jm] = dupf(As[(mb + jm) * ASTR + i]);
#pragma unroll
        for (int jm = 0; jm < 4; ++jm) {
            ffma2(ra[jm * 2 + 0], ap[jm], wr.x);
            ffma2(ra[jm * 2 + 1], ap[jm], wr.y);
            ffma2(za[jm * 2 + 0], ap[jm], wz.x);
            ffma2(za[jm * 2 + 1], ap[jm], wz.y);
        }
    }

    // Epilogue r/z: write RC = r * cur; keep z in registers.
    float zz[16];
#pragma unroll
    for (int jm = 0; jm < 4; ++jm) {
        const int m = mb + jm;
        float4 rc4;
        float rcv[4];
#pragma unroll
        for (int p = 0; p < 2; ++p) {
            const float2 rv = unpk(ra[jm * 2 + p]);
            const float2 zv = unpk(za[jm * 2 + p]);
            const int o0 = ob + p * 2;
            const float r0 = sigm(rv.x + __ldg(&b_r[o0]));
            const float r1 = sigm(rv.y + __ldg(&b_r[o0 + 1]));
            zz[jm * 4 + p * 2 + 0] = sigm(zv.x + __ldg(&b_z[o0]));
            zz[jm * 4 + p * 2 + 1] = sigm(zv.y + __ldg(&b_z[o0 + 1]));
            rcv[p * 2 + 0] = r0 * As[m * ASTR + 128 + o0];
            rcv[p * 2 + 1] = r1 * As[m * ASTR + 128 + o0 + 1];
        }
        rc4.x = rcv[0]; rc4.y = rcv[1]; rc4.z = rcv[2]; rc4.w = rcv[3];
        *reinterpret_cast<float4*>(&RC[m * RSTR + ob]) = rc4;
    }
    __syncthreads();

    // Loop C: finish h with the r*cur columns.
#pragma unroll 2
    for (int i = 128; i < KDIM; ++i) {
        const ulonglong2 wh = __ldg(reinterpret_cast<const ulonglong2*>(Wh + i * DD + ob));
        u64t ap[4];
#pragma unroll
        for (int jm = 0; jm < 4; ++jm) ap[jm] = dupf(RC[(mb + jm) * RSTR + (i - 128)]);
#pragma unroll
        for (int jm = 0; jm < 4; ++jm) {
            ffma2(ha[jm * 2 + 0], ap[jm], wh.x);
            ffma2(ha[jm * 2 + 1], ap[jm], wh.y);
        }
    }

    // ---------- Epilogue: GRU combine + store ----------
#pragma unroll
    for (int jm = 0; jm < 4; ++jm) {
        const int m    = mb + jm;
        const int node = m >> 3;
        const int l    = m & 7;
        const int gn   = nb + node;
        float tmp[4];
#pragma unroll
        for (int p = 0; p < 2; ++p) {
            const float2 hv = unpk(ha[jm * 2 + p]);
            const int o0 = ob + p * 2;
            const float h0 = tanhf(hv.x + __ldg(&b_h[o0]));
            const float h1 = tanhf(hv.y + __ldg(&b_h[o0 + 1]));
            const float z0 = zz[jm * 4 + p * 2 + 0];
            const float z1 = zz[jm * 4 + p * 2 + 1];
            const float c0 = As[m * ASTR + 128 + o0];
            const float c1 = As[m * ASTR + 128 + o0 + 1];
            tmp[p * 2 + 0] = (1.0f - z0) * c0 + z0 * h0;
            tmp[p * 2 + 1] = (1.0f - z1) * c1 + z1 * h1;
        }
        float4 o4 = {tmp[0], tmp[1], tmp[2], tmp[3]};
        float* dst = out + ((size_t)(b * NN + gn) * LL + l) * DD + ob;
        *reinterpret_cast<float4*>(dst) = o4;
    }
}

// ---------------- launch ----------------
extern "C" void kernel_launch(void* const* d_in, const int* in_sizes, int n_in,
                              void* d_out, int out_size) {
    (void)in_sizes; (void)n_in; (void)out_size;
    const float* state_in  = (const float*)d_in[0];
    const float* state_out = (const float*)d_in[1];
    const float* state_cur = (const float*)d_in[2];
    const float* A_vals    = (const float*)d_in[3];
    const int*   A_rows    = (const int*)  d_in[4];
    const int*   A_cols    = (const int*)  d_in[5];
    const float* W_r       = (const float*)d_in[6];
    const float* b_r       = (const float*)d_in[7];
    const float* W_z       = (const float*)d_in[8];
    const float* b_z       = (const float*)d_in[9];
    const float* W_h       = (const float*)d_in[10];
    const float* b_h       = (const float*)d_in[11];
    float* out = (float*)d_out;

    const int smem_bytes = (64 * ASTR + 64 * RSTR) * sizeof(float);
    cudaFuncSetAttribute(k_main, cudaFuncAttributeMaxDynamicSharedMemorySize, smem_bytes);

    k_zero_counts<<<(SEG * NN + 255) / 256, 256>>>();
    k_hist<<<(SEG * NNZE + 255) / 256, 256>>>(A_rows);
    k_scan<<<SEG, 256>>>();
    k_scatter<<<(SEG * NNZE + 255) / 256, 256>>>(A_vals, A_rows, A_cols);
    k_wt<<<(3 * KDIM * DD + 255) / 256, 256>>>(W_r, W_z, W_h);
    k_main<<<BB * (NN / NPB), 256, smem_bytes>>>(state_in, state_out, state_cur,
                                                 b_r, b_z, b_h, out);
}

// round 4
// speedup vs baseline: 2.0962x; 2.0962x over previous
#include <cuda_runtime.h>
#include <cuda_bf16.h>
#include <cstdint>

// ---------------- problem constants ----------------
#define BB   8
#define NT   2
#define NN   2000
#define ENN  4000
#define NNZE 32000
#define LL   8
#define DD   64
#define LD   512
#define SEG  (BB*NT)
#define NPB  8             // nodes per block -> M = 64
#define NBLK (NN/NPB)      // 250
#define KD   192

// A smem: 64 rows x 200 bf16 slots (400 B/row, 192 used). hi then lo.
#define AROW 200
#define A_BYTES (64 * AROW * 2)      // 25600
#define SMEM_TOTAL (2 * A_BYTES)     // 51200

// ---------------- device scratch ----------------
__device__ int   g_count [SEG * NN];
__device__ int   g_cursor[SEG * NN];
__device__ int   g_rowptr[SEG * (NN + 1)];
__device__ float g_ev    [SEG * NNZE];
__device__ int   g_ec    [SEG * NNZE];
// W images: [mat(3)][n(64)][k(192)] bf16, hi and lo
__device__ __align__(16) __nv_bfloat16 g_Wb_hi[3 * 64 * 192];
__device__ __align__(16) __nv_bfloat16 g_Wb_lo[3 * 64 * 192];

// ---------------- helpers ----------------
__device__ __forceinline__ uint32_t smem_u32(const void* p) {
    uint32_t a;
    asm("{ .reg .u64 t; cvta.to.shared.u64 t, %1; cvt.u32.u64 %0, t; }" : "=r"(a) : "l"(p));
    return a;
}
__device__ __forceinline__ float sigm(float x) { return 1.0f / (1.0f + __expf(-x)); }

#define LDMATRIX_X4(r0, r1, r2, r3, addr) \
    asm volatile("ldmatrix.sync.aligned.m8n8.x4.shared.b16 {%0,%1,%2,%3}, [%4];" \
        : "=r"(r0), "=r"(r1), "=r"(r2), "=r"(r3) : "r"(addr))

#define MMA16816(c, a0, a1, a2, a3, b0, b1) \
    asm volatile("mma.sync.aligned.m16n8k16.row.col.f32.bf16.bf16.f32 " \
        "{%0,%1,%2,%3}, {%4,%5,%6,%7}, {%8,%9}, {%0,%1,%2,%3};" \
        : "+f"((c)[0]), "+f"((c)[1]), "+f"((c)[2]), "+f"((c)[3]) \
        : "r"(a0), "r"(a1), "r"(a2), "r"(a3), "r"(b0), "r"(b1))

// ---------------- CSR build (proven) ----------------
__global__ void k_zero_counts() {
    int i = blockIdx.x * blockDim.x + threadIdx.x;
    if (i < SEG * NN) g_count[i] = 0;
}
__global__ void k_hist(const int* __restrict__ rows) {
    int idx = blockIdx.x * blockDim.x + threadIdx.x;
    if (idx >= SEG * NNZE) return;
    int seg = idx / NNZE;
    atomicAdd(&g_count[seg * NN + rows[idx]], 1);
}
__global__ void k_scan() {
    int seg = blockIdx.x;
    int t   = threadIdx.x;
    __shared__ int sm2[256];
    int c[8];
    int ts = 0;
    int base = seg * NN;
#pragma unroll
    for (int j = 0; j < 8; ++j) {
        int idx = t * 8 + j;
        c[j] = (idx < NN) ? g_count[base + idx] : 0;
        ts += c[j];
    }
    sm2[t] = ts;
    __syncthreads();
    for (int off = 1; off < 256; off <<= 1) {
        int v = sm2[t];
        if (t >= off) v += sm2[t - off];
        __syncthreads();
        sm2[t] = v;
        __syncthreads();
    }
    int run = sm2[t] - ts;
#pragma unroll
    for (int j = 0; j < 8; ++j) {
        int idx = t * 8 + j;
        if (idx < NN) {
            g_rowptr[seg * (NN + 1) + idx] = run;
            g_cursor[base + idx] = run;
            run += c[j];
        }
    }
    if (t == 255) g_rowptr[seg * (NN + 1) + NN] = sm2[255];
}
__global__ void k_scatter(const float* __restrict__ vals,
                          const int*   __restrict__ rows,
                          const int*   __restrict__ cols) {
    int idx = blockIdx.x * blockDim.x + threadIdx.x;
    if (idx >= SEG * NNZE) return;
    int seg = idx / NNZE;
    int pos = atomicAdd(&g_cursor[seg * NN + rows[idx]], 1);
    g_ev[seg * NNZE + pos] = vals[idx];
    g_ec[seg * NNZE + pos] = cols[idx];
}

// ---------------- W prep: bf16 hi/lo images, layout [mat][n][k] ----------------
__global__ void k_wprep(const float* __restrict__ Wr,
                        const float* __restrict__ Wz,
                        const float* __restrict__ Wh) {
    int idx = blockIdx.x * blockDim.x + threadIdx.x;
    if (idx >= 3 * 64 * 192) return;
    int mat = idx / (64 * 192);
    int r   = idx - mat * (64 * 192);     // n*192 + k  == source offset
    const float* W = (mat == 0) ? Wr : (mat == 1) ? Wz : Wh;
    float w = W[r];
    __nv_bfloat16 hi = __float2bfloat16(w);
    __nv_bfloat16 lo = __float2bfloat16(w - __bfloat162float(hi));
    g_Wb_hi[idx] = hi;
    g_Wb_lo[idx] = lo;
}

// ---------------- main fused kernel ----------------
__global__ void __launch_bounds__(256)
k_main(const float* __restrict__ state_in,
       const float* __restrict__ state_out,
       const float* __restrict__ state_cur,
       const float* __restrict__ b_r,
       const float* __restrict__ b_z,
       const float* __restrict__ b_h,
       float* __restrict__ out) {
    extern __shared__ char smem[];
    __nv_bfloat16* Ah = reinterpret_cast<__nv_bfloat16*>(smem);
    __nv_bfloat16* Al = reinterpret_cast<__nv_bfloat16*>(smem + A_BYTES);
    const uint32_t sbh = smem_u32(smem);
    const uint32_t sbl = sbh + A_BYTES;

    const int tid  = threadIdx.x;
    const int w    = tid >> 5;
    const int lane = tid & 31;
    const int b    = blockIdx.x / NBLK;
    const int nb   = (blockIdx.x - b * NBLK) * NPB;

    // ---------- Phase 1: SpMM gather -> bf16 hi/lo A tiles ----------
    for (int task = w; task < 16; task += 8) {
        const int node = task >> 1;
        const int type = task & 1;
        const int n    = nb + node;
        const int seg  = b * NT + type;
        const int start = g_rowptr[seg * (NN + 1) + n];
        const int end   = g_rowptr[seg * (NN + 1) + n + 1];
        const float* S  = (type == 0 ? state_in : state_out) + (size_t)b * ENN * LD;

        float4 a0 = {0,0,0,0}, a1 = {0,0,0,0}, a2 = {0,0,0,0}, a3 = {0,0,0,0};
        int   k = start;
        float v = 0.0f;
        int   c = 0;
        if (k < end) { v = g_ev[seg * NNZE + k]; c = g_ec[seg * NNZE + k]; }
        for (; k < end; ++k) {
            const float cv = v;
            const int   cc = c;
            if (k + 1 < end) {
                v = g_ev[seg * NNZE + k + 1];
                c = g_ec[seg * NNZE + k + 1];
            }
            const float4* row = reinterpret_cast<const float4*>(S + (size_t)cc * LD);
            float4 r0 = __ldg(row + lane);
            float4 r1 = __ldg(row + 32 + lane);
            float4 r2 = __ldg(row + 64 + lane);
            float4 r3 = __ldg(row + 96 + lane);
            a0.x += cv * r0.x; a0.y += cv * r0.y; a0.z += cv * r0.z; a0.w += cv * r0.w;
            a1.x += cv * r1.x; a1.y += cv * r1.y; a1.z += cv * r1.z; a1.w += cv * r1.w;
            a2.x += cv * r2.x; a2.y += cv * r2.y; a2.z += cv * r2.z; a2.w += cv * r2.w;
            a3.x += cv * r3.x; a3.y += cv * r3.y; a3.z += cv * r3.z; a3.w += cv * r3.w;
        }
        float4 acc[4] = {a0, a1, a2, a3};
#pragma unroll
        for (int j = 0; j < 4; ++j) {
            const int E   = j * 32 + lane;
            const int l   = E >> 4;
            const int d4  = (E & 15) * 4;
            const int row = node * LL + l;
            const int kb  = type * DD + d4;
            float4 vx = acc[j];
            __nv_bfloat162 h01 = __floats2bfloat162_rn(vx.x, vx.y);
            __nv_bfloat162 h23 = __floats2bfloat162_rn(vx.z, vx.w);
            __nv_bfloat162 l01 = __floats2bfloat162_rn(vx.x - __bfloat162float(h01.x),
                                                       vx.y - __bfloat162float(h01.y));
            __nv_bfloat162 l23 = __floats2bfloat162_rn(vx.z - __bfloat162float(h23.x),
                                                       vx.w - __bfloat162float(h23.y));
            uint2 hw, lw;
            hw.x = *reinterpret_cast<uint32_t*>(&h01);
            hw.y = *reinterpret_cast<uint32_t*>(&h23);
            lw.x = *reinterpret_cast<uint32_t*>(&l01);
            lw.y = *reinterpret_cast<uint32_t*>(&l23);
            *reinterpret_cast<uint2*>(&Ah[row * AROW + kb]) = hw;
            *reinterpret_cast<uint2*>(&Al[row * AROW + kb]) = lw;
        }
    }
    // state_cur: warp w loads node w
    {
        const int n = nb + w;
        const float4* C = reinterpret_cast<const float4*>(state_cur + (size_t)(b * NN + n) * LD);
#pragma unroll
        for (int j = 0; j < 4; ++j) {
            const int E   = j * 32 + lane;
            const int l   = E >> 4;
            const int d4  = (E & 15) * 4;
            float4 vx = __ldg(C + E);
            const int row = w * LL + l;
            const int kb  = 128 + d4;
            __nv_bfloat162 h01 = __floats2bfloat162_rn(vx.x, vx.y);
            __nv_bfloat162 h23 = __floats2bfloat162_rn(vx.z, vx.w);
            __nv_bfloat162 l01 = __floats2bfloat162_rn(vx.x - __bfloat162float(h01.x),
                                                       vx.y - __bfloat162float(h01.y));
            __nv_bfloat162 l23 = __floats2bfloat162_rn(vx.z - __bfloat162float(h23.x),
                                                       vx.w - __bfloat162float(h23.y));
            uint2 hw, lw;
            hw.x = *reinterpret_cast<uint32_t*>(&h01);
            hw.y = *reinterpret_cast<uint32_t*>(&h23);
            lw.x = *reinterpret_cast<uint32_t*>(&l01);
            lw.y = *reinterpret_cast<uint32_t*>(&l23);
            *reinterpret_cast<uint2*>(&Ah[row * AROW + kb]) = hw;
            *reinterpret_cast<uint2*>(&Al[row * AROW + kb]) = lw;
        }
    }
    __syncthreads();

    // ---------- Phase 2: HMMA GEMMs ----------
    // Warp w: n-cols [8w, 8w+8) of r, z, h. M = 64 (4 m16 tiles). K tiles of 16.
    const int n0 = w * 8;
    const int qr = lane >> 2;          // 0..7 : n offset within tile AND a-frag row group
    const int qc = (lane & 3) * 2;     // 0,2,4,6 : k offset (b-frag), c-frag col base

    float cr[16], cz[16], ch[16];
#pragma unroll
    for (int i = 0; i < 16; ++i) { cr[i] = 0.0f; cz[i] = 0.0f; ch[i] = 0.0f; }

    const int arow = lane & 15;
    const int koff16 = ((lane >> 4) & 1) * 16;   // +16 bytes for k 8..15 halves
    const int bnr = (n0 + qr) * 192 + qc;        // element offset for mat 0

    // Main loop part 1: kt 0..7 (r, z, h)
#pragma unroll
    for (int kt = 0; kt < 8; ++kt) {
        const int k0 = kt * 16;
        const uint32_t brh0 = *reinterpret_cast<const uint32_t*>(g_Wb_hi + bnr + k0);
        const uint32_t brh1 = *reinterpret_cast<const uint32_t*>(g_Wb_hi + bnr + k0 + 8);
        const uint32_t brl0 = *reinterpret_cast<const uint32_t*>(g_Wb_lo + bnr + k0);
        const uint32_t brl1 = *reinterpret_cast<const uint32_t*>(g_Wb_lo + bnr + k0 + 8);
        const uint32_t bzh0 = *reinterpret_cast<const uint32_t*>(g_Wb_hi + 64*192 + bnr + k0);
        const uint32_t bzh1 = *reinterpret_cast<const uint32_t*>(g_Wb_hi + 64*192 + bnr + k0 + 8);
        const uint32_t bzl0 = *reinterpret_cast<const uint32_t*>(g_Wb_lo + 64*192 + bnr + k0);
        const uint32_t bzl1 = *reinterpret_cast<const uint32_t*>(g_Wb_lo + 64*192 + bnr + k0 + 8);
        const uint32_t bhh0 = *reinterpret_cast<const uint32_t*>(g_Wb_hi + 128*192 + bnr + k0);
        const uint32_t bhh1 = *reinterpret_cast<const uint32_t*>(g_Wb_hi + 128*192 + bnr + k0 + 8);
        const uint32_t bhl0 = *reinterpret_cast<const uint32_t*>(g_Wb_lo + 128*192 + bnr + k0);
        const uint32_t bhl1 = *reinterpret_cast<const uint32_t*>(g_Wb_lo + 128*192 + bnr + k0 + 8);
#pragma unroll
        for (int i = 0; i < 4; ++i) {
            const uint32_t aoff = (uint32_t)((16 * i + arow) * 400 + k0 * 2 + koff16);
            uint32_t ah0, ah1, ah2, ah3, al0, al1, al2, al3;
            LDMATRIX_X4(ah0, ah1, ah2, ah3, sbh + aoff);
            LDMATRIX_X4(al0, al1, al2, al3, sbl + aoff);
            MMA16816(cr + 4*i, ah0, ah1, ah2, ah3, brh0, brh1);
            MMA16816(cr + 4*i, al0, al1, al2, al3, brh0, brh1);
            MMA16816(cr + 4*i, ah0, ah1, ah2, ah3, brl0, brl1);
            MMA16816(cz + 4*i, ah0, ah1, ah2, ah3, bzh0, bzh1);
            MMA16816(cz + 4*i, al0, al1, al2, al3, bzh0, bzh1);
            MMA16816(cz + 4*i, ah0, ah1, ah2, ah3, bzl0, bzl1);
            MMA16816(ch + 4*i, ah0, ah1, ah2, ah3, bhh0, bhh1);
            MMA16816(ch + 4*i, al0, al1, al2, al3, bhh0, bhh1);
            MMA16816(ch + 4*i, ah0, ah1, ah2, ah3, bhl0, bhl1);
        }
    }
    // Main loop part 2: kt 8..11 (r, z only)
#pragma unroll
    for (int kt = 8; kt < 12; ++kt) {
        const int k0 = kt * 16;
        const uint32_t brh0 = *reinterpret_cast<const uint32_t*>(g_Wb_hi + bnr + k0);
        const uint32_t brh1 = *reinterpret_cast<const uint32_t*>(g_Wb_hi + bnr + k0 + 8);
        const uint32_t brl0 = *reinterpret_cast<const uint32_t*>(g_Wb_lo + bnr + k0);
        const uint32_t brl1 = *reinterpret_cast<const uint32_t*>(g_Wb_lo + bnr + k0 + 8);
        const uint32_t bzh0 = *reinterpret_cast<const uint32_t*>(g_Wb_hi + 64*192 + bnr + k0);
        const uint32_t bzh1 = *reinterpret_cast<const uint32_t*>(g_Wb_hi + 64*192 + bnr + k0 + 8);
        const uint32_t bzl0 = *reinterpret_cast<const uint32_t*>(g_Wb_lo + 64*192 + bnr + k0);
        const uint32_t bzl1 = *reinterpret_cast<const uint32_t*>(g_Wb_lo + 64*192 + bnr + k0 + 8);
#pragma unroll
        for (int i = 0; i < 4; ++i) {
            const uint32_t aoff = (uint32_t)((16 * i + arow) * 400 + k0 * 2 + koff16);
            uint32_t ah0, ah1, ah2, ah3, al0, al1, al2, al3;
            LDMATRIX_X4(ah0, ah1, ah2, ah3, sbh + aoff);
            LDMATRIX_X4(al0, al1, al2, al3, sbl + aoff);
            MMA16816(cr + 4*i, ah0, ah1, ah2, ah3, brh0, brh1);
            MMA16816(cr + 4*i, al0, al1, al2, al3, brh0, brh1);
            MMA16816(cr + 4*i, ah0, ah1, ah2, ah3, brl0, brl1);
            MMA16816(cz + 4*i, ah0, ah1, ah2, ah3, bzh0, bzh1);
            MMA16816(cz + 4*i, al0, al1, al2, al3, bzh0, bzh1);
            MMA16816(cz + 4*i, ah0, ah1, ah2, ah3, bzl0, bzl1);
        }
    }
    __syncthreads();   // all r/z reads of cur columns done before rc overwrite

    // ---------- Epilogue 1: r, z; write rc = r*cur over cur columns ----------
    float curv[16], zreg[16];
#pragma unroll
    for (int i = 0; i < 4; ++i) {
#pragma unroll
        for (int rr = 0; rr < 2; ++rr) {
            const int m = 16 * i + qr + 8 * rr;
#pragma unroll
            for (int cc = 0; cc < 2; ++cc) {
                const int o   = n0 + qc + cc;
                const int idx = i * 4 + rr * 2 + cc;
                const int e   = m * AROW + 128 + o;
                const float cur = __bfloat162float(Ah[e]) + __bfloat162float(Al[e]);
                curv[idx] = cur;
                const float rv = sigm(cr[idx] + __ldg(&b_r[o]));
                zreg[idx] = sigm(cz[idx] + __ldg(&b_z[o]));
                const float rc = rv * cur;
                const __nv_bfloat16 hi = __float2bfloat16(rc);
                Ah[e] = hi;
                Al[e] = __float2bfloat16(rc - __bfloat162float(hi));
            }
        }
    }
    __syncthreads();

    // ---------- Phase 3: finish h with rc columns (kt 8..11) ----------
#pragma unroll
    for (int kt = 8; kt < 12; ++kt) {
        const int k0 = kt * 16;
        const uint32_t bhh0 = *reinterpret_cast<const uint32_t*>(g_Wb_hi + 128*192 + bnr + k0);
        const uint32_t bhh1 = *reinterpret_cast<const uint32_t*>(g_Wb_hi + 128*192 + bnr + k0 + 8);
        const uint32_t bhl0 = *reinterpret_cast<const uint32_t*>(g_Wb_lo + 128*192 + bnr + k0);
        const uint32_t bhl1 = *reinterpret_cast<const uint32_t*>(g_Wb_lo + 128*192 + bnr + k0 + 8);
#pragma unroll
        for (int i = 0; i < 4; ++i) {
            const uint32_t aoff = (uint32_t)((16 * i + arow) * 400 + k0 * 2 + koff16);
            uint32_t ah0, ah1, ah2, ah3, al0, al1, al2, al3;
            LDMATRIX_X4(ah0, ah1, ah2, ah3, sbh + aoff);
            LDMATRIX_X4(al0, al1, al2, al3, sbl + aoff);
            MMA16816(ch + 4*i, ah0, ah1, ah2, ah3, bhh0, bhh1);
            MMA16816(ch + 4*i, al0, al1, al2, al3, bhh0, bhh1);
            MMA16816(ch + 4*i, ah0, ah1, ah2, ah3, bhl0, bhl1);
        }
    }

    // ---------- Epilogue 2: GRU combine + store ----------
#pragma unroll
    for (int i = 0; i < 4; ++i) {
#pragma unroll
        for (int rr = 0; rr < 2; ++rr) {
            const int m    = 16 * i + qr + 8 * rr;
            const int node = m >> 3;
            const int l    = m & 7;
            const size_t grow = ((size_t)(b * NN + nb + node) * LL + l);
            float2 v;
#pragma unroll
            for (int cc = 0; cc < 2; ++cc) {
                const int o   = n0 + qc + cc;
                const int idx = i * 4 + rr * 2 + cc;
                const float h = tanhf(ch[idx] + __ldg(&b_h[o]));
                const float z = zreg[idx];
                const float r2 = (1.0f - z) * curv[idx] + z * h;
                if (cc == 0) v.x = r2; else v.y = r2;
            }
            *reinterpret_cast<float2*>(out + grow * DD + n0 + qc) = v;
        }
    }
}

// ---------------- launch ----------------
extern "C" void kernel_launch(void* const* d_in, const int* in_sizes, int n_in,
                              void* d_out, int out_size) {
    (void)in_sizes; (void)n_in; (void)out_size;
    const float* state_in  = (const float*)d_in[0];
    const float* state_out = (const float*)d_in[1];
    const float* state_cur = (const float*)d_in[2];
    const float* A_vals    = (const float*)d_in[3];
    const int*   A_rows    = (const int*)  d_in[4];
    const int*   A_cols    = (const int*)  d_in[5];
    const float* W_r       = (const float*)d_in[6];
    const float* b_r       = (const float*)d_in[7];
    const float* W_z       = (const float*)d_in[8];
    const float* b_z       = (const float*)d_in[9];
    const float* W_h       = (const float*)d_in[10];
    const float* b_h       = (const float*)d_in[11];
    float* out = (float*)d_out;

    cudaFuncSetAttribute(k_main, cudaFuncAttributeMaxDynamicSharedMemorySize, SMEM_TOTAL);

    k_zero_counts<<<(SEG * NN + 255) / 256, 256>>>();
    k_hist<<<(SEG * NNZE + 255) / 256, 256>>>(A_rows);
    k_scan<<<SEG, 256>>>();
    k_scatter<<<(SEG * NNZE + 255) / 256, 256>>>(A_vals, A_rows, A_cols);
    k_wprep<<<(3 * 64 * 192 + 255) / 256, 256>>>(W_r, W_z, W_h);
    k_main<<<BB * NBLK, 256, SMEM_TOTAL>>>(state_in, state_out, state_cur,
                                           b_r, b_z, b_h, out);
}

// round 5
// speedup vs baseline: 2.1513x; 1.0263x over previous
#include <cuda_runtime.h>
#include <cuda_bf16.h>
#include <cstdint>

// ---------------- problem constants ----------------
#define BB   8
#define NT   2
#define NN   2000
#define ENN  4000
#define NNZE 32000
#define LL   8
#define DD   64
#define LD   512
#define SEG  (BB*NT)
#define NPB  8             // nodes per block -> M = 64
#define NBLK (NN/NPB)      // 250
#define KD   192

// A smem: 64 rows x 200 bf16 slots (400 B/row, 192 used). hi then lo.
#define AROW 200
#define A_BYTES (64 * AROW * 2)      // 25600
#define SMEM_TOTAL (2 * A_BYTES)     // 51200

// ---------------- device scratch ----------------
__device__ int   g_count [SEG * NN];
__device__ int   g_cursor[SEG * NN];
__device__ int   g_rowptr[SEG * (NN + 1)];
__device__ float g_ev    [SEG * NNZE];
__device__ int   g_ec    [SEG * NNZE];
// W images: [mat(3)][n(64)][k(192)] bf16, hi and lo
__device__ __align__(16) __nv_bfloat16 g_Wb_hi[3 * 64 * 192];
__device__ __align__(16) __nv_bfloat16 g_Wb_lo[3 * 64 * 192];

// ---------------- helpers ----------------
__device__ __forceinline__ uint32_t smem_u32(const void* p) {
    uint32_t a;
    asm("{ .reg .u64 t; cvta.to.shared.u64 t, %1; cvt.u32.u64 %0, t; }" : "=r"(a) : "l"(p));
    return a;
}
__device__ __forceinline__ float sigm(float x) { return 1.0f / (1.0f + __expf(-x)); }

#define LDMATRIX_X4(r0, r1, r2, r3, addr) \
    asm volatile("ldmatrix.sync.aligned.m8n8.x4.shared.b16 {%0,%1,%2,%3}, [%4];" \
        : "=r"(r0), "=r"(r1), "=r"(r2), "=r"(r3) : "r"(addr))

#define MMA16816(c, a0, a1, a2, a3, b0, b1) \
    asm volatile("mma.sync.aligned.m16n8k16.row.col.f32.bf16.bf16.f32 " \
        "{%0,%1,%2,%3}, {%4,%5,%6,%7}, {%8,%9}, {%0,%1,%2,%3};" \
        : "+f"((c)[0]), "+f"((c)[1]), "+f"((c)[2]), "+f"((c)[3]) \
        : "r"(a0), "r"(a1), "r"(a2), "r"(a3), "r"(b0), "r"(b1))

// ---------------- init: zero counts + W prep (fused) ----------------
__global__ void k_init(const float* __restrict__ Wr,
                       const float* __restrict__ Wz,
                       const float* __restrict__ Wh) {
    int idx = blockIdx.x * blockDim.x + threadIdx.x;
    if (idx < SEG * NN) g_count[idx] = 0;
    if (idx < 3 * 64 * 192) {
        int mat = idx / (64 * 192);
        int r   = idx - mat * (64 * 192);
        const float* W = (mat == 0) ? Wr : (mat == 1) ? Wz : Wh;
        float w = W[r];
        __nv_bfloat16 hi = __float2bfloat16(w);
        __nv_bfloat16 lo = __float2bfloat16(w - __bfloat162float(hi));
        g_Wb_hi[idx] = hi;
        g_Wb_lo[idx] = lo;
    }
}

__global__ void k_hist(const int* __restrict__ rows) {
    int idx = blockIdx.x * blockDim.x + threadIdx.x;
    if (idx >= SEG * NNZE) return;
    int seg = idx / NNZE;
    atomicAdd(&g_count[seg * NN + rows[idx]], 1);
}
__global__ void k_scan() {
    int seg = blockIdx.x;
    int t   = threadIdx.x;
    __shared__ int sm2[256];
    int c[8];
    int ts = 0;
    int base = seg * NN;
#pragma unroll
    for (int j = 0; j < 8; ++j) {
        int idx = t * 8 + j;
        c[j] = (idx < NN) ? g_count[base + idx] : 0;
        ts += c[j];
    }
    sm2[t] = ts;
    __syncthreads();
    for (int off = 1; off < 256; off <<= 1) {
        int v = sm2[t];
        if (t >= off) v += sm2[t - off];
        __syncthreads();
        sm2[t] = v;
        __syncthreads();
    }
    int run = sm2[t] - ts;
#pragma unroll
    for (int j = 0; j < 8; ++j) {
        int idx = t * 8 + j;
        if (idx < NN) {
            g_rowptr[seg * (NN + 1) + idx] = run;
            g_cursor[base + idx] = run;
            run += c[j];
        }
    }
    if (t == 255) g_rowptr[seg * (NN + 1) + NN] = sm2[255];
}
__global__ void k_scatter(const float* __restrict__ vals,
                          const int*   __restrict__ rows,
                          const int*   __restrict__ cols) {
    int idx = blockIdx.x * blockDim.x + threadIdx.x;
    if (idx >= SEG * NNZE) return;
    int seg = idx / NNZE;
    int pos = atomicAdd(&g_cursor[seg * NN + rows[idx]], 1);
    g_ev[seg * NNZE + pos] = vals[idx];
    g_ec[seg * NNZE + pos] = cols[idx];
}

// ---------------- main fused kernel ----------------
__global__ void __launch_bounds__(256)
k_main(const float* __restrict__ state_in,
       const float* __restrict__ state_out,
       const float* __restrict__ state_cur,
       const float* __restrict__ b_r,
       const float* __restrict__ b_z,
       const float* __restrict__ b_h,
       float* __restrict__ out) {
    extern __shared__ char smem[];
    __nv_bfloat16* Ah = reinterpret_cast<__nv_bfloat16*>(smem);
    __nv_bfloat16* Al = reinterpret_cast<__nv_bfloat16*>(smem + A_BYTES);
    const uint32_t sbh = smem_u32(smem);
    const uint32_t sbl = sbh + A_BYTES;

    const int tid  = threadIdx.x;
    const int w    = tid >> 5;
    const int lane = tid & 31;
    const int b    = blockIdx.x / NBLK;
    const int nb   = (blockIdx.x - b * NBLK) * NPB;

    // ---------- Phase 1: SpMM gather (2-edge unrolled, deep MLP) ----------
    for (int task = w; task < 16; task += 8) {
        const int node = task >> 1;
        const int type = task & 1;
        const int n    = nb + node;
        const int seg  = b * NT + type;
        const int start = g_rowptr[seg * (NN + 1) + n];
        const int end   = g_rowptr[seg * (NN + 1) + n + 1];
        const float* S  = (type == 0 ? state_in : state_out) + (size_t)b * ENN * LD;
        const float* EV = g_ev + seg * NNZE;
        const int*   EC = g_ec + seg * NNZE;

        float4 a0 = {0,0,0,0}, a1 = {0,0,0,0}, a2 = {0,0,0,0}, a3 = {0,0,0,0};

        int   k   = start;
        int   rem = end - start;
        float v0 = 0.0f, v1 = 0.0f;
        int   c0 = 0,    c1 = 0;
        if (rem > 0) { v0 = EV[k];     c0 = EC[k]; }
        if (rem > 1) { v1 = EV[k + 1]; c1 = EC[k + 1]; }

        while (rem >= 2) {
            // prefetch next pair
            float nv0 = 0.0f, nv1 = 0.0f;
            int   nc0 = 0,    nc1 = 0;
            if (rem > 2) { nv0 = EV[k + 2]; nc0 = EC[k + 2]; }
            if (rem > 3) { nv1 = EV[k + 3]; nc1 = EC[k + 3]; }

            const float4* ra = reinterpret_cast<const float4*>(S + (size_t)c0 * LD);
            const float4* rb = reinterpret_cast<const float4*>(S + (size_t)c1 * LD);
            float4 xa0 = __ldg(ra + lane);
            float4 xa1 = __ldg(ra + 32 + lane);
            float4 xa2 = __ldg(ra + 64 + lane);
            float4 xa3 = __ldg(ra + 96 + lane);
            float4 xb0 = __ldg(rb + lane);
            float4 xb1 = __ldg(rb + 32 + lane);
            float4 xb2 = __ldg(rb + 64 + lane);
            float4 xb3 = __ldg(rb + 96 + lane);

            a0.x += v0 * xa0.x; a0.y += v0 * xa0.y; a0.z += v0 * xa0.z; a0.w += v0 * xa0.w;
            a1.x += v0 * xa1.x; a1.y += v0 * xa1.y; a1.z += v0 * xa1.z; a1.w += v0 * xa1.w;
            a2.x += v0 * xa2.x; a2.y += v0 * xa2.y; a2.z += v0 * xa2.z; a2.w += v0 * xa2.w;
            a3.x += v0 * xa3.x; a3.y += v0 * xa3.y; a3.z += v0 * xa3.z; a3.w += v0 * xa3.w;
            a0.x += v1 * xb0.x; a0.y += v1 * xb0.y; a0.z += v1 * xb0.z; a0.w += v1 * xb0.w;
            a1.x += v1 * xb1.x; a1.y += v1 * xb1.y; a1.z += v1 * xb1.z; a1.w += v1 * xb1.w;
            a2.x += v1 * xb2.x; a2.y += v1 * xb2.y; a2.z += v1 * xb2.z; a2.w += v1 * xb2.w;
            a3.x += v1 * xb3.x; a3.y += v1 * xb3.y; a3.z += v1 * xb3.z; a3.w += v1 * xb3.w;

            v0 = nv0; c0 = nc0; v1 = nv1; c1 = nc1;
            k += 2; rem -= 2;
        }
        if (rem == 1) {
            const float4* ra = reinterpret_cast<const float4*>(S + (size_t)c0 * LD);
            float4 xa0 = __ldg(ra + lane);
            float4 xa1 = __ldg(ra + 32 + lane);
            float4 xa2 = __ldg(ra + 64 + lane);
            float4 xa3 = __ldg(ra + 96 + lane);
            a0.x += v0 * xa0.x; a0.y += v0 * xa0.y; a0.z += v0 * xa0.z; a0.w += v0 * xa0.w;
            a1.x += v0 * xa1.x; a1.y += v0 * xa1.y; a1.z += v0 * xa1.z; a1.w += v0 * xa1.w;
            a2.x += v0 * xa2.x; a2.y += v0 * xa2.y; a2.z += v0 * xa2.z; a2.w += v0 * xa2.w;
            a3.x += v0 * xa3.x; a3.y += v0 * xa3.y; a3.z += v0 * xa3.z; a3.w += v0 * xa3.w;
        }

        float4 acc[4] = {a0, a1, a2, a3};
#pragma unroll
        for (int j = 0; j < 4; ++j) {
            const int E   = j * 32 + lane;
            const int l   = E >> 4;
            const int d4  = (E & 15) * 4;
            const int row = node * LL + l;
            const int kb  = type * DD + d4;
            float4 vx = acc[j];
            __nv_bfloat162 h01 = __floats2bfloat162_rn(vx.x, vx.y);
            __nv_bfloat162 h23 = __floats2bfloat162_rn(vx.z, vx.w);
            __nv_bfloat162 l01 = __floats2bfloat162_rn(vx.x - __bfloat162float(h01.x),
                                                       vx.y - __bfloat162float(h01.y));
            __nv_bfloat162 l23 = __floats2bfloat162_rn(vx.z - __bfloat162float(h23.x),
                                                       vx.w - __bfloat162float(h23.y));
            uint2 hw, lw;
            hw.x = *reinterpret_cast<uint32_t*>(&h01);
            hw.y = *reinterpret_cast<uint32_t*>(&h23);
            lw.x = *reinterpret_cast<uint32_t*>(&l01);
            lw.y = *reinterpret_cast<uint32_t*>(&l23);
            *reinterpret_cast<uint2*>(&Ah[row * AROW + kb]) = hw;
            *reinterpret_cast<uint2*>(&Al[row * AROW + kb]) = lw;
        }
    }
    // state_cur: warp w loads node w
    {
        const int n = nb + w;
        const float4* C = reinterpret_cast<const float4*>(state_cur + (size_t)(b * NN + n) * LD);
#pragma unroll
        for (int j = 0; j < 4; ++j) {
            const int E   = j * 32 + lane;
            const int l   = E >> 4;
            const int d4  = (E & 15) * 4;
            float4 vx = __ldg(C + E);
            const int row = w * LL + l;
            const int kb  = 128 + d4;
            __nv_bfloat162 h01 = __floats2bfloat162_rn(vx.x, vx.y);
            __nv_bfloat162 h23 = __floats2bfloat162_rn(vx.z, vx.w);
            __nv_bfloat162 l01 = __floats2bfloat162_rn(vx.x - __bfloat162float(h01.x),
                                                       vx.y - __bfloat162float(h01.y));
            __nv_bfloat162 l23 = __floats2bfloat162_rn(vx.z - __bfloat162float(h23.x),
                                                       vx.w - __bfloat162float(h23.y));
            uint2 hw, lw;
            hw.x = *reinterpret_cast<uint32_t*>(&h01);
            hw.y = *reinterpret_cast<uint32_t*>(&h23);
            lw.x = *reinterpret_cast<uint32_t*>(&l01);
            lw.y = *reinterpret_cast<uint32_t*>(&l23);
            *reinterpret_cast<uint2*>(&Ah[row * AROW + kb]) = hw;
            *reinterpret_cast<uint2*>(&Al[row * AROW + kb]) = lw;
        }
    }
    __syncthreads();

    // ---------- Phase 2: HMMA GEMMs ----------
    const int n0 = w * 8;
    const int qr = lane >> 2;
    const int qc = (lane & 3) * 2;

    float cr[16], cz[16], ch[16];
#pragma unroll
    for (int i = 0; i < 16; ++i) { cr[i] = 0.0f; cz[i] = 0.0f; ch[i] = 0.0f; }

    const int arow = lane & 15;
    const int koff16 = ((lane >> 4) & 1) * 16;
    const int bnr = (n0 + qr) * 192 + qc;

#pragma unroll
    for (int kt = 0; kt < 8; ++kt) {
        const int k0 = kt * 16;
        const uint32_t brh0 = *reinterpret_cast<const uint32_t*>(g_Wb_hi + bnr + k0);
        const uint32_t brh1 = *reinterpret_cast<const uint32_t*>(g_Wb_hi + bnr + k0 + 8);
        const uint32_t brl0 = *reinterpret_cast<const uint32_t*>(g_Wb_lo + bnr + k0);
        const uint32_t brl1 = *reinterpret_cast<const uint32_t*>(g_Wb_lo + bnr + k0 + 8);
        const uint32_t bzh0 = *reinterpret_cast<const uint32_t*>(g_Wb_hi + 64*192 + bnr + k0);
        const uint32_t bzh1 = *reinterpret_cast<const uint32_t*>(g_Wb_hi + 64*192 + bnr + k0 + 8);
        const uint32_t bzl0 = *reinterpret_cast<const uint32_t*>(g_Wb_lo + 64*192 + bnr + k0);
        const uint32_t bzl1 = *reinterpret_cast<const uint32_t*>(g_Wb_lo + 64*192 + bnr + k0 + 8);
        const uint32_t bhh0 = *reinterpret_cast<const uint32_t*>(g_Wb_hi + 128*192 + bnr + k0);
        const uint32_t bhh1 = *reinterpret_cast<const uint32_t*>(g_Wb_hi + 128*192 + bnr + k0 + 8);
        const uint32_t bhl0 = *reinterpret_cast<const uint32_t*>(g_Wb_lo + 128*192 + bnr + k0);
        const uint32_t bhl1 = *reinterpret_cast<const uint32_t*>(g_Wb_lo + 128*192 + bnr + k0 + 8);
#pragma unroll
        for (int i = 0; i < 4; ++i) {
            const uint32_t aoff = (uint32_t)((16 * i + arow) * 400 + k0 * 2 + koff16);
            uint32_t ah0, ah1, ah2, ah3, al0, al1, al2, al3;
            LDMATRIX_X4(ah0, ah1, ah2, ah3, sbh + aoff);
            LDMATRIX_X4(al0, al1, al2, al3, sbl + aoff);
            MMA16816(cr + 4*i, ah0, ah1, ah2, ah3, brh0, brh1);
            MMA16816(cr + 4*i, al0, al1, al2, al3, brh0, brh1);
            MMA16816(cr + 4*i, ah0, ah1, ah2, ah3, brl0, brl1);
            MMA16816(cz + 4*i, ah0, ah1, ah2, ah3, bzh0, bzh1);
            MMA16816(cz + 4*i, al0, al1, al2, al3, bzh0, bzh1);
            MMA16816(cz + 4*i, ah0, ah1, ah2, ah3, bzl0, bzl1);
            MMA16816(ch + 4*i, ah0, ah1, ah2, ah3, bhh0, bhh1);
            MMA16816(ch + 4*i, al0, al1, al2, al3, bhh0, bhh1);
            MMA16816(ch + 4*i, ah0, ah1, ah2, ah3, bhl0, bhl1);
        }
    }
#pragma unroll
    for (int kt = 8; kt < 12; ++kt) {
        const int k0 = kt * 16;
        const uint32_t brh0 = *reinterpret_cast<const uint32_t*>(g_Wb_hi + bnr + k0);
        const uint32_t brh1 = *reinterpret_cast<const uint32_t*>(g_Wb_hi + bnr + k0 + 8);
        const uint32_t brl0 = *reinterpret_cast<const uint32_t*>(g_Wb_lo + bnr + k0);
        const uint32_t brl1 = *reinterpret_cast<const uint32_t*>(g_Wb_lo + bnr + k0 + 8);
        const uint32_t bzh0 = *reinterpret_cast<const uint32_t*>(g_Wb_hi + 64*192 + bnr + k0);
        const uint32_t bzh1 = *reinterpret_cast<const uint32_t*>(g_Wb_hi + 64*192 + bnr + k0 + 8);
        const uint32_t bzl0 = *reinterpret_cast<const uint32_t*>(g_Wb_lo + 64*192 + bnr + k0);
        const uint32_t bzl1 = *reinterpret_cast<const uint32_t*>(g_Wb_lo + 64*192 + bnr + k0 + 8);
#pragma unroll
        for (int i = 0; i < 4; ++i) {
            const uint32_t aoff = (uint32_t)((16 * i + arow) * 400 + k0 * 2 + koff16);
            uint32_t ah0, ah1, ah2, ah3, al0, al1, al2, al3;
            LDMATRIX_X4(ah0, ah1, ah2, ah3, sbh + aoff);
            LDMATRIX_X4(al0, al1, al2, al3, sbl + aoff);
            MMA16816(cr + 4*i, ah0, ah1, ah2, ah3, brh0, brh1);
            MMA16816(cr + 4*i, al0, al1, al2, al3, brh0, brh1);
            MMA16816(cr + 4*i, ah0, ah1, ah2, ah3, brl0, brl1);
            MMA16816(cz + 4*i, ah0, ah1, ah2, ah3, bzh0, bzh1);
            MMA16816(cz + 4*i, al0, al1, al2, al3, bzh0, bzh1);
            MMA16816(cz + 4*i, ah0, ah1, ah2, ah3, bzl0, bzl1);
        }
    }
    __syncthreads();

    // ---------- Epilogue 1: r, z; write rc = r*cur over cur columns ----------
    float curv[16], zreg[16];
#pragma unroll
    for (int i = 0; i < 4; ++i) {
#pragma unroll
        for (int rr = 0; rr < 2; ++rr) {
            const int m = 16 * i + qr + 8 * rr;
#pragma unroll
            for (int cc = 0; cc < 2; ++cc) {
                const int o   = n0 + qc + cc;
                const int idx = i * 4 + rr * 2 + cc;
                const int e   = m * AROW + 128 + o;
                const float cur = __bfloat162float(Ah[e]) + __bfloat162float(Al[e]);
                curv[idx] = cur;
                const float rv = sigm(cr[idx] + __ldg(&b_r[o]));
                zreg[idx] = sigm(cz[idx] + __ldg(&b_z[o]));
                const float rc = rv * cur;
                const __nv_bfloat16 hi = __float2bfloat16(rc);
                Ah[e] = hi;
                Al[e] = __float2bfloat16(rc - __bfloat162float(hi));
            }
        }
    }
    __syncthreads();

    // ---------- Phase 3: finish h with rc columns ----------
#pragma unroll
    for (int kt = 8; kt < 12; ++kt) {
        const int k0 = kt * 16;
        const uint32_t bhh0 = *reinterpret_cast<const uint32_t*>(g_Wb_hi + 128*192 + bnr + k0);
        const uint32_t bhh1 = *reinterpret_cast<const uint32_t*>(g_Wb_hi + 128*192 + bnr + k0 + 8);
        const uint32_t bhl0 = *reinterpret_cast<const uint32_t*>(g_Wb_lo + 128*192 + bnr + k0);
        const uint32_t bhl1 = *reinterpret_cast<const uint32_t*>(g_Wb_lo + 128*192 + bnr + k0 + 8);
#pragma unroll
        for (int i = 0; i < 4; ++i) {
            const uint32_t aoff = (uint32_t)((16 * i + arow) * 400 + k0 * 2 + koff16);
            uint32_t ah0, ah1, ah2, ah3, al0, al1, al2, al3;
            LDMATRIX_X4(ah0, ah1, ah2, ah3, sbh + aoff);
            LDMATRIX_X4(al0, al1, al2, al3, sbl + aoff);
            MMA16816(ch + 4*i, ah0, ah1, ah2, ah3, bhh0, bhh1);
            MMA16816(ch + 4*i, al0, al1, al2, al3, bhh0, bhh1);
            MMA16816(ch + 4*i, ah0, ah1, ah2, ah3, bhl0, bhl1);
        }
    }

    // ---------- Epilogue 2: GRU combine + store ----------
#pragma unroll
    for (int i = 0; i < 4; ++i) {
#pragma unroll
        for (int rr = 0; rr < 2; ++rr) {
            const int m    = 16 * i + qr + 8 * rr;
            const int node = m >> 3;
            const int l    = m & 7;
            const size_t grow = ((size_t)(b * NN + nb + node) * LL + l);
            float2 v;
#pragma unroll
            for (int cc = 0; cc < 2; ++cc) {
                const int o   = n0 + qc + cc;
                const int idx = i * 4 + rr * 2 + cc;
                const float h = tanhf(ch[idx] + __ldg(&b_h[o]));
                const float z = zreg[idx];
                const float r2 = (1.0f - z) * curv[idx] + z * h;
                if (cc == 0) v.x = r2; else v.y = r2;
            }
            *reinterpret_cast<float2*>(out + grow * DD + n0 + qc) = v;
        }
    }
}

// ---------------- launch ----------------
extern "C" void kernel_launch(void* const* d_in, const int* in_sizes, int n_in,
                              void* d_out, int out_size) {
    (void)in_sizes; (void)n_in; (void)out_size;
    const float* state_in  = (const float*)d_in[0];
    const float* state_out = (const float*)d_in[1];
    const float* state_cur = (const float*)d_in[2];
    const float* A_vals    = (const float*)d_in[3];
    const int*   A_rows    = (const int*)  d_in[4];
    const int*   A_cols    = (const int*)  d_in[5];
    const float* W_r       = (const float*)d_in[6];
    const float* b_r       = (const float*)d_in[7];
    const float* W_z       = (const float*)d_in[8];
    const float* b_z       = (const float*)d_in[9];
    const float* W_h       = (const float*)d_in[10];
    const float* b_h       = (const float*)d_in[11];
    float* out = (float*)d_out;

    cudaFuncSetAttribute(k_main, cudaFuncAttributeMaxDynamicSharedMemorySize, SMEM_TOTAL);

    k_init<<<(3 * 64 * 192 + 255) / 256, 256>>>(W_r, W_z, W_h);
    k_hist<<<(SEG * NNZE + 255) / 256, 256>>>(A_rows);
    k_scan<<<SEG, 256>>>();
    k_scatter<<<(SEG * NNZE + 255) / 256, 256>>>(A_vals, A_rows, A_cols);
    k_main<<<BB * NBLK, 256, SMEM_TOTAL>>>(state_in, state_out, state_cur,
                                           b_r, b_z, b_h, out);
}